// round 6
// baseline (speedup 1.0000x reference)
#include <cuda_runtime.h>
#include <cuda_bf16.h>
#include <cstdint>

#define N_NODES 50000
#define N_EDGES 800000
#define NODE_IN 128
#define EDGE_IN 16
#define HIDDEN  128
#define OUT_DIM 128
#define KDIM    (NODE_IN + EDGE_IN)   // 144

// ---------------- scratch (device globals; no allocation allowed) ----------------
__device__ __align__(16) float g_A[(size_t)N_NODES * KDIM];   // [aggX | aggE], stride 144
__device__ __align__(16) float g_h[(size_t)N_NODES * HIDDEN]; // relu(layer1)
__device__ int g_count[N_NODES];
__device__ int g_rowstart[N_NODES];
__device__ int g_cursor[N_NODES];
__device__ int g_perm[N_EDGES];   // edge id, sorted by dst
__device__ int g_src[N_EDGES];    // src node id, sorted by dst
__device__ int g_blocksums[128];
__device__ int g_blockoff[128];
__device__ int g_is64;

// ---------------- dtype detect + zero counts (fused) ----------------
// int64 indices in [0,50000) => every odd 32-bit word is 0.
__global__ void k_init(const int* __restrict__ ei) {
    int i = blockIdx.x * blockDim.x + threadIdx.x;
    if (i < N_NODES) g_count[i] = 0;
    if (blockIdx.x == 0) {
        __shared__ int found;
        if (threadIdx.x == 0) found = 0;
        __syncthreads();
        for (int k = threadIdx.x; k < 4096; k += blockDim.x) {
            if (ei[2 * k + 1] != 0) atomicOr(&found, 1);
        }
        __syncthreads();
        if (threadIdx.x == 0) g_is64 = found ? 0 : 1;
    }
}

__device__ __forceinline__ int load_idx(const int* ei, size_t elem, int is64) {
    return is64 ? ei[2 * elem] : ei[elem];
}

// ---------------- CSR build ----------------
__global__ void k_hist(const int* __restrict__ ei) {
    int e = blockIdx.x * blockDim.x + threadIdx.x;
    if (e >= N_EDGES) return;
    int is64 = g_is64;
    int d = load_idx(ei, (size_t)N_EDGES + e, is64);
    atomicAdd(&g_count[d], 1);
}

__global__ void k_scan1() {
    __shared__ int s[512];
    int t = threadIdx.x;
    int i = blockIdx.x * 512 + t;
    int v = (i < N_NODES) ? g_count[i] : 0;
    s[t] = v;
    __syncthreads();
    for (int off = 1; off < 512; off <<= 1) {
        int tmp = (t >= off) ? s[t - off] : 0;
        __syncthreads();
        s[t] += tmp;
        __syncthreads();
    }
    if (i < N_NODES) g_rowstart[i] = s[t] - v;
    if (t == 511) g_blocksums[blockIdx.x] = s[511];
}

__global__ void k_scan2(int nblocks) {
    __shared__ int s[128];
    int t = threadIdx.x;
    int v = (t < nblocks) ? g_blocksums[t] : 0;
    s[t] = v;
    __syncthreads();
    for (int off = 1; off < 128; off <<= 1) {
        int tmp = (t >= off) ? s[t - off] : 0;
        __syncthreads();
        s[t] += tmp;
        __syncthreads();
    }
    if (t < nblocks) g_blockoff[t] = s[t] - v;
}

__global__ void k_scan3() {
    int i = blockIdx.x * 512 + threadIdx.x;
    if (i < N_NODES) {
        int r = g_rowstart[i] + g_blockoff[blockIdx.x];
        g_rowstart[i] = r;
        g_cursor[i] = r;
    }
}

__global__ void k_scatter(const int* __restrict__ ei) {
    int e = blockIdx.x * blockDim.x + threadIdx.x;
    if (e >= N_EDGES) return;
    int is64 = g_is64;
    int d = load_idx(ei, (size_t)N_EDGES + e, is64);
    int s = load_idx(ei, (size_t)e, is64);
    int pos = atomicAdd(&g_cursor[d], 1);
    g_perm[pos] = e;
    g_src[pos] = s;
}

// ---------------- aggregation: warp per node, 4-wide unrolled ----------------
// Sums src-node features (128 f32 = one float4 per lane) into g_A[:, 0:128].
// If WITH_EA, lanes 0..15 also sum edge_attr (16 f32) into g_A[:, 128:144].
template <bool WITH_EA>
__global__ __launch_bounds__(256) void k_agg(const float* __restrict__ feat,
                                             const float* __restrict__ ea) {
    int warp = (blockIdx.x * blockDim.x + threadIdx.x) >> 5;
    int lane = threadIdx.x & 31;
    if (warp >= N_NODES) return;

    int start = g_rowstart[warp];
    int cnt = g_count[warp];
    const float4* xf = (const float4*)feat;
    const bool do_ea = WITH_EA && (lane < 16);

    float4 a0 = make_float4(0.f, 0.f, 0.f, 0.f);
    float4 a1 = make_float4(0.f, 0.f, 0.f, 0.f);
    float4 a2 = make_float4(0.f, 0.f, 0.f, 0.f);
    float4 a3 = make_float4(0.f, 0.f, 0.f, 0.f);
    float e0acc = 0.f, e1acc = 0.f, e2acc = 0.f, e3acc = 0.f;

    int i = 0;
    for (; i + 4 <= cnt; i += 4) {
        // 4 independent index loads (broadcast within warp)
        int s0 = g_src[start + i + 0];
        int s1 = g_src[start + i + 1];
        int s2 = g_src[start + i + 2];
        int s3 = g_src[start + i + 3];
        int p0 = 0, p1 = 0, p2 = 0, p3 = 0;
        if (WITH_EA) {
            p0 = g_perm[start + i + 0];
            p1 = g_perm[start + i + 1];
            p2 = g_perm[start + i + 2];
            p3 = g_perm[start + i + 3];
        }
        // 4 independent feature gathers -> MLP 4+
        float4 v0 = xf[(size_t)s0 * 32 + lane];
        float4 v1 = xf[(size_t)s1 * 32 + lane];
        float4 v2 = xf[(size_t)s2 * 32 + lane];
        float4 v3 = xf[(size_t)s3 * 32 + lane];
        a0.x += v0.x; a0.y += v0.y; a0.z += v0.z; a0.w += v0.w;
        a1.x += v1.x; a1.y += v1.y; a1.z += v1.z; a1.w += v1.w;
        a2.x += v2.x; a2.y += v2.y; a2.z += v2.z; a2.w += v2.w;
        a3.x += v3.x; a3.y += v3.y; a3.z += v3.z; a3.w += v3.w;
        if (do_ea) {
            e0acc += ea[(size_t)p0 * EDGE_IN + lane];
            e1acc += ea[(size_t)p1 * EDGE_IN + lane];
            e2acc += ea[(size_t)p2 * EDGE_IN + lane];
            e3acc += ea[(size_t)p3 * EDGE_IN + lane];
        }
    }
    for (; i < cnt; i++) {
        int s0 = g_src[start + i];
        float4 v0 = xf[(size_t)s0 * 32 + lane];
        a0.x += v0.x; a0.y += v0.y; a0.z += v0.z; a0.w += v0.w;
        if (do_ea) {
            int p0 = g_perm[start + i];
            e0acc += ea[(size_t)p0 * EDGE_IN + lane];
        }
    }

    float4 acc;
    acc.x = (a0.x + a1.x) + (a2.x + a3.x);
    acc.y = (a0.y + a1.y) + (a2.y + a3.y);
    acc.z = (a0.z + a1.z) + (a2.z + a3.z);
    acc.w = (a0.w + a1.w) + (a2.w + a3.w);

    ((float4*)(g_A + (size_t)warp * KDIM))[lane] = acc;
    if (do_ea)
        g_A[(size_t)warp * KDIM + NODE_IN + lane] = (e0acc + e1acc) + (e2acc + e3acc);
}

// ================= tensor-core GEMM via mma.sync (sm_80+ path) ================
// C[M,128] = A[M,144] @ W[144,128] + b, optional relu.
// bf16 3-pass split: A=Ah+Al, B=Bh+Bl; D = Ah*Bh + Ah*Bl + Al*Bh, fp32 accum.
// Whole K resident in SMEM. Padded stride 152 bf16 -> conflict-free frag loads.

#define SM_STRIDE 152                       // bf16 elements per row (padded)
#define PLANE     (128 * SM_STRIDE)         // elements per plane
#define GEMM_DYN_SMEM (4 * PLANE * 2)       // 4 planes of bf16 = 155648 B

#define MMA16816(d, a, b)                                                     \
    asm volatile(                                                             \
        "mma.sync.aligned.m16n8k16.row.col.f32.bf16.bf16.f32 "                \
        "{%0,%1,%2,%3}, {%4,%5,%6,%7}, {%8,%9}, {%0,%1,%2,%3};"               \
        : "+f"((d)[0]), "+f"((d)[1]), "+f"((d)[2]), "+f"((d)[3])              \
        : "r"((a)[0]), "r"((a)[1]), "r"((a)[2]), "r"((a)[3]),                 \
          "r"((b)[0]), "r"((b)[1]))

__device__ __forceinline__ uint32_t pack_bf16x2(__nv_bfloat16 lo, __nv_bfloat16 hi) {
    __nv_bfloat162 p = __halves2bfloat162(lo, hi);   // .x = lo addr half
    return *(uint32_t*)&p;
}

__global__ __launch_bounds__(256, 1)
void k_gemm_mma(const float* __restrict__ A,
                const float* __restrict__ W,
                const float* __restrict__ bias,
                float* __restrict__ C,
                int M, int relu) {
    extern __shared__ __align__(16) char smraw[];
    __nv_bfloat16* sAh = (__nv_bfloat16*)smraw;       // [128 m][152 k]
    __nv_bfloat16* sAl = sAh + PLANE;
    __nv_bfloat16* sBh = sAl + PLANE;                 // [128 n][152 k] (= W^T)
    __nv_bfloat16* sBl = sBh + PLANE;

    const int tid = threadIdx.x;
    const int m0 = blockIdx.x * 128;

    // ---- stage A tile: rows m0..m0+127, k 0..143, hi/lo split ----
    for (int idx = tid; idx < 128 * 72; idx += 256) {     // 72 float2 per row
        int r = idx / 72;
        int kc = (idx - r * 72) * 2;
        int gr = m0 + r;
        float2 v = make_float2(0.f, 0.f);
        if (gr < M) v = *(const float2*)(A + (size_t)gr * KDIM + kc);
        __nv_bfloat16 h0 = __float2bfloat16(v.x);
        __nv_bfloat16 h1 = __float2bfloat16(v.y);
        __nv_bfloat16 l0 = __float2bfloat16(v.x - __bfloat162float(h0));
        __nv_bfloat16 l1 = __float2bfloat16(v.y - __bfloat162float(h1));
        int o = r * SM_STRIDE + kc;
        *(uint32_t*)(sAh + o) = pack_bf16x2(h0, h1);
        *(uint32_t*)(sAl + o) = pack_bf16x2(l0, l1);
    }
    // ---- stage B tile: B^T[n][k] = W[k][n], hi/lo split ----
    for (int idx = tid; idx < KDIM * 128; idx += 256) {
        int k = idx >> 7;          // W row
        int n = idx & 127;         // W col (coalesced global read)
        float v = W[idx];
        __nv_bfloat16 h = __float2bfloat16(v);
        __nv_bfloat16 l = __float2bfloat16(v - __bfloat162float(h));
        int o = n * SM_STRIDE + k;
        sBh[o] = h;
        sBl[o] = l;
    }
    __syncthreads();

    // ---- mma mainloop ----
    const int wid = tid >> 5;
    const int lane = tid & 31;
    const int g = lane >> 2;        // group id (0..7)
    const int t = lane & 3;         // thread in group
    const int wm = (wid >> 2) * 64; // warp M offset (0/64)
    const int wn = (wid & 3) * 32;  // warp N offset (0/32/64/96)

    float acc[4][4][4];
#pragma unroll
    for (int i = 0; i < 4; i++)
#pragma unroll
        for (int j = 0; j < 4; j++)
#pragma unroll
            for (int q = 0; q < 4; q++) acc[i][j][q] = 0.f;

#pragma unroll
    for (int ks = 0; ks < 9; ks++) {
        const int kb = ks * 16;     // k base (bf16 elems)
        uint32_t ah[4][4], al[4][4], bh[4][2], bl[4][2];
#pragma unroll
        for (int i = 0; i < 4; i++) {
            int r = wm + i * 16;
            int o0 = (r + g) * SM_STRIDE + kb + 2 * t;
            int o1 = (r + g + 8) * SM_STRIDE + kb + 2 * t;
            ah[i][0] = *(const uint32_t*)(sAh + o0);
            ah[i][1] = *(const uint32_t*)(sAh + o1);
            ah[i][2] = *(const uint32_t*)(sAh + o0 + 8);
            ah[i][3] = *(const uint32_t*)(sAh + o1 + 8);
            al[i][0] = *(const uint32_t*)(sAl + o0);
            al[i][1] = *(const uint32_t*)(sAl + o1);
            al[i][2] = *(const uint32_t*)(sAl + o0 + 8);
            al[i][3] = *(const uint32_t*)(sAl + o1 + 8);
        }
#pragma unroll
        for (int j = 0; j < 4; j++) {
            int n = wn + j * 8 + g;
            int o = n * SM_STRIDE + kb + 2 * t;
            bh[j][0] = *(const uint32_t*)(sBh + o);
            bh[j][1] = *(const uint32_t*)(sBh + o + 8);
            bl[j][0] = *(const uint32_t*)(sBl + o);
            bl[j][1] = *(const uint32_t*)(sBl + o + 8);
        }
#pragma unroll
        for (int i = 0; i < 4; i++)
#pragma unroll
            for (int j = 0; j < 4; j++) {
                MMA16816(acc[i][j], ah[i], bh[j]);
                MMA16816(acc[i][j], ah[i], bl[j]);
                MMA16816(acc[i][j], al[i], bh[j]);
            }
    }

    // ---- epilogue: bias + relu, direct global stores (float2) ----
#pragma unroll
    for (int j = 0; j < 4; j++) {
        int c = wn + j * 8 + 2 * t;
        float2 bb = *(const float2*)(bias + c);
#pragma unroll
        for (int i = 0; i < 4; i++) {
            int r0 = m0 + wm + i * 16 + g;
            float v0 = acc[i][j][0] + bb.x;
            float v1 = acc[i][j][1] + bb.y;
            float v2 = acc[i][j][2] + bb.x;
            float v3 = acc[i][j][3] + bb.y;
            if (relu) {
                v0 = fmaxf(v0, 0.f); v1 = fmaxf(v1, 0.f);
                v2 = fmaxf(v2, 0.f); v3 = fmaxf(v3, 0.f);
            }
            if (r0 < M)
                *(float2*)(C + (size_t)r0 * 128 + c) = make_float2(v0, v1);
            if (r0 + 8 < M)
                *(float2*)(C + (size_t)(r0 + 8) * 128 + c) = make_float2(v2, v3);
        }
    }
}

// ---------------- launch ----------------
extern "C" void kernel_launch(void* const* d_in, const int* in_sizes, int n_in,
                              void* d_out, int out_size) {
    const float* x  = (const float*)d_in[0];
    const int*   ei = (const int*)d_in[1];
    const float* ea = (const float*)d_in[2];
    const float* W1 = (const float*)d_in[3];
    const float* b1 = (const float*)d_in[4];
    const float* W2 = (const float*)d_in[5];
    const float* b2 = (const float*)d_in[6];
    float* out = (float*)d_out;

    const int NB_SCAN = (N_NODES + 511) / 512;
    const int EB = (N_EDGES + 255) / 256;
    const int AGG_B = (N_NODES * 32 + 255) / 256;
    const int GEMM_B = (N_NODES + 127) / 128;   // 391

    void* p;
    cudaGetSymbolAddress(&p, g_A); float* s_A = (float*)p;
    cudaGetSymbolAddress(&p, g_h); float* s_h = (float*)p;

    cudaFuncSetAttribute(k_gemm_mma, cudaFuncAttributeMaxDynamicSharedMemorySize,
                         GEMM_DYN_SMEM);

    k_init<<<(N_NODES + 255) / 256, 256>>>(ei);
    k_hist<<<EB, 256>>>(ei);
    k_scan1<<<NB_SCAN, 512>>>();
    k_scan2<<<1, 128>>>(NB_SCAN);
    k_scan3<<<NB_SCAN, 512>>>();
    k_scatter<<<EB, 256>>>(ei);

    // layer 1: aggregate x + edge_attr, then mma GEMM with relu -> g_h
    k_agg<true><<<AGG_B, 256>>>(x, ea);
    k_gemm_mma<<<GEMM_B, 256, GEMM_DYN_SMEM>>>(s_A, W1, b1, s_h, N_NODES, 1);

    // layer 2: aggregate h into cols 0..127 (edge cols 128..143 preserved)
    k_agg<false><<<AGG_B, 256>>>(s_h, nullptr);
    k_gemm_mma<<<GEMM_B, 256, GEMM_DYN_SMEM>>>(s_A, W2, b2, out, N_NODES, 0);
}

// round 8
// speedup vs baseline: 1.0327x; 1.0327x over previous
#include <cuda_runtime.h>
#include <cuda_bf16.h>
#include <cstdint>

#define N_NODES 50000
#define N_EDGES 800000
#define NODE_IN 128
#define EDGE_IN 16
#define HIDDEN  128
#define OUT_DIM 128
#define KDIM    (NODE_IN + EDGE_IN)   // 144

#define CSR_BLOCKS 98
#define CSR_THREADS 512

// ---------------- scratch (device globals; no allocation allowed) ----------------
__device__ __align__(16) float g_A[(size_t)N_NODES * KDIM];   // [aggX | aggE], stride 144
__device__ __align__(16) float g_h[(size_t)N_NODES * HIDDEN]; // relu(layer1)
__device__ int g_count[N_NODES];
__device__ int g_rowstart[N_NODES];
__device__ int g_cursor[N_NODES];
__device__ int g_perm[N_EDGES];   // edge id, sorted by dst
__device__ int g_src[N_EDGES];    // src node id, sorted by dst
__device__ int g_blocksums[CSR_BLOCKS];
__device__ int g_is64;
__device__ unsigned g_bar[8];     // monotonic grid-barrier counters (never reset)

// ---------------- grid quasi-barrier (co-resident grid only) ----------------
// Monotonic counter: each launch adds exactly nblk arrivals; target is the
// next multiple of nblk at-or-above our arrival. Replay-safe, no reset.
__device__ __forceinline__ void grid_barrier(int i, unsigned nblk) {
    __syncthreads();
    if (threadIdx.x == 0) {
        __threadfence();
        unsigned old = atomicAdd(&g_bar[i], 1u) + 1u;
        unsigned target = ((old + nblk - 1u) / nblk) * nblk;
        while (atomicAdd(&g_bar[i], 0u) < target) { }
        __threadfence();
    }
    __syncthreads();
}

__device__ __forceinline__ int load_idx(const int* ei, size_t elem, int is64) {
    return is64 ? ei[2 * elem] : ei[elem];
}

// ---------------- fused CSR build: detect+zero | hist | scan | scatter -------
__global__ __launch_bounds__(CSR_THREADS) void k_csr(const int* __restrict__ ei) {
    const int tid = threadIdx.x;
    const int bid = blockIdx.x;
    const int gid = bid * CSR_THREADS + tid;
    const int nthreads = CSR_BLOCKS * CSR_THREADS;   // 50176

    __shared__ int s[CSR_THREADS];
    __shared__ int s_prefix;
    __shared__ int s_found;

    // ---- phase 0: zero counts + dtype detect (block 0) ----
    if (gid < N_NODES) g_count[gid] = 0;
    if (bid == 0) {
        if (tid == 0) s_found = 0;
        __syncthreads();
        for (int k = tid; k < 4096; k += CSR_THREADS)
            if (ei[2 * k + 1] != 0) atomicOr(&s_found, 1);
        __syncthreads();
        if (tid == 0) g_is64 = s_found ? 0 : 1;
    }
    grid_barrier(0, CSR_BLOCKS);

    // ---- phase 1: histogram of dst ----
    const int is64 = g_is64;
    for (int e = gid; e < N_EDGES; e += nthreads) {
        int d = load_idx(ei, (size_t)N_EDGES + e, is64);
        atomicAdd(&g_count[d], 1);
    }
    grid_barrier(1, CSR_BLOCKS);

    // ---- phase 2a: block-local inclusive scan of counts ----
    int i = gid;
    int v = (i < N_NODES) ? g_count[i] : 0;
    s[tid] = v;
    __syncthreads();
    for (int off = 1; off < CSR_THREADS; off <<= 1) {
        int tmp = (tid >= off) ? s[tid - off] : 0;
        __syncthreads();
        s[tid] += tmp;
        __syncthreads();
    }
    int local_excl = s[tid] - v;
    if (tid == CSR_THREADS - 1) g_blocksums[bid] = s[tid];
    grid_barrier(2, CSR_BLOCKS);

    // ---- phase 2b: block prefix over blocksums (serial, 98 adds) ----
    if (tid == 0) {
        int p = 0;
        for (int b = 0; b < bid; b++) p += g_blocksums[b];
        s_prefix = p;
    }
    __syncthreads();
    if (i < N_NODES) {
        int r = local_excl + s_prefix;
        g_rowstart[i] = r;
        g_cursor[i] = r;
    }
    grid_barrier(3, CSR_BLOCKS);

    // ---- phase 3: scatter edges into CSR order ----
    for (int e = gid; e < N_EDGES; e += nthreads) {
        int d = load_idx(ei, (size_t)N_EDGES + e, is64);
        int sidx = load_idx(ei, (size_t)e, is64);
        int pos = atomicAdd(&g_cursor[d], 1);
        g_perm[pos] = e;
        g_src[pos] = sidx;
    }
}

// ---------------- aggregation: warp per node (round-5 proven form) -----------
// Sums src-node features (128 f32 = one float4 per lane) into g_A[:, 0:128].
// If WITH_EA, lanes 0..15 also sum edge_attr (16 f32) into g_A[:, 128:144].
template <bool WITH_EA>
__global__ __launch_bounds__(256) void k_agg(const float* __restrict__ feat,
                                             const float* __restrict__ ea) {
    int warp = (blockIdx.x * blockDim.x + threadIdx.x) >> 5;
    int lane = threadIdx.x & 31;
    if (warp >= N_NODES) return;

    int start = g_rowstart[warp];
    int cnt = g_count[warp];
    const float4* xf = (const float4*)feat;

    float4 acc = make_float4(0.f, 0.f, 0.f, 0.f);
    float eacc = 0.f;
    bool do_ea = WITH_EA && (lane < 16);

    int s = 0, e = 0;
    if (cnt > 0) {
        s = g_src[start];
        if (WITH_EA) e = g_perm[start];
    }
    for (int i = 0; i < cnt; i++) {
        int s2 = 0, e2 = 0;
        if (i + 1 < cnt) {
            s2 = g_src[start + i + 1];
            if (WITH_EA) e2 = g_perm[start + i + 1];
        }
        float4 v = xf[(size_t)s * 32 + lane];
        acc.x += v.x; acc.y += v.y; acc.z += v.z; acc.w += v.w;
        if (do_ea) eacc += ea[(size_t)e * EDGE_IN + lane];
        s = s2; e = e2;
    }

    ((float4*)(g_A + (size_t)warp * KDIM))[lane] = acc;
    if (do_ea) g_A[(size_t)warp * KDIM + NODE_IN + lane] = eacc;
}

// ================= tensor-core GEMM via mma.sync (sm_80+ path) ================
// C[M,128] = A[M,144] @ W[144,128] + b, optional relu.
// bf16 3-pass split: A=Ah+Al, B=Bh+Bl; D = Ah*Bh + Ah*Bl + Al*Bh, fp32 accum.
// Whole K resident in SMEM. Padded stride 152 bf16 -> conflict-free frag loads.

#define SM_STRIDE 152                       // bf16 elements per row (padded)
#define PLANE     (128 * SM_STRIDE)         // elements per plane
#define GEMM_DYN_SMEM (4 * PLANE * 2)       // 4 planes of bf16 = 155648 B

#define MMA16816(d, a, b)                                                     \
    asm volatile(                                                             \
        "mma.sync.aligned.m16n8k16.row.col.f32.bf16.bf16.f32 "                \
        "{%0,%1,%2,%3}, {%4,%5,%6,%7}, {%8,%9}, {%0,%1,%2,%3};"               \
        : "+f"((d)[0]), "+f"((d)[1]), "+f"((d)[2]), "+f"((d)[3])              \
        : "r"((a)[0]), "r"((a)[1]), "r"((a)[2]), "r"((a)[3]),                 \
          "r"((b)[0]), "r"((b)[1]))

__device__ __forceinline__ uint32_t pack_bf16x2(__nv_bfloat16 lo, __nv_bfloat16 hi) {
    __nv_bfloat162 p = __halves2bfloat162(lo, hi);   // .x = lo addr half
    return *(uint32_t*)&p;
}

__global__ __launch_bounds__(256, 1)
void k_gemm_mma(const float* __restrict__ A,
                const float* __restrict__ W,
                const float* __restrict__ bias,
                float* __restrict__ C,
                int M, int relu) {
    extern __shared__ __align__(16) char smraw[];
    __nv_bfloat16* sAh = (__nv_bfloat16*)smraw;       // [128 m][152 k]
    __nv_bfloat16* sAl = sAh + PLANE;
    __nv_bfloat16* sBh = sAl + PLANE;                 // [128 n][152 k] (= W^T)
    __nv_bfloat16* sBl = sBh + PLANE;

    const int tid = threadIdx.x;
    const int m0 = blockIdx.x * 128;

    // ---- stage A tile: rows m0..m0+127, k 0..143, hi/lo split ----
    for (int idx = tid; idx < 128 * 72; idx += 256) {     // 72 float2 per row
        int r = idx / 72;
        int kc = (idx - r * 72) * 2;
        int gr = m0 + r;
        float2 v = make_float2(0.f, 0.f);
        if (gr < M) v = *(const float2*)(A + (size_t)gr * KDIM + kc);
        __nv_bfloat16 h0 = __float2bfloat16(v.x);
        __nv_bfloat16 h1 = __float2bfloat16(v.y);
        __nv_bfloat16 l0 = __float2bfloat16(v.x - __bfloat162float(h0));
        __nv_bfloat16 l1 = __float2bfloat16(v.y - __bfloat162float(h1));
        int o = r * SM_STRIDE + kc;
        *(uint32_t*)(sAh + o) = pack_bf16x2(h0, h1);
        *(uint32_t*)(sAl + o) = pack_bf16x2(l0, l1);
    }
    // ---- stage B tile: B^T[n][k] = W[k][n], hi/lo split ----
    for (int idx = tid; idx < KDIM * 128; idx += 256) {
        int k = idx >> 7;          // W row
        int n = idx & 127;         // W col (coalesced global read)
        float v = W[idx];
        __nv_bfloat16 h = __float2bfloat16(v);
        __nv_bfloat16 l = __float2bfloat16(v - __bfloat162float(h));
        int o = n * SM_STRIDE + k;
        sBh[o] = h;
        sBl[o] = l;
    }
    __syncthreads();

    // ---- mma mainloop ----
    const int wid = tid >> 5;
    const int lane = tid & 31;
    const int g = lane >> 2;        // group id (0..7)
    const int t = lane & 3;         // thread in group
    const int wm = (wid >> 2) * 64; // warp M offset (0/64)
    const int wn = (wid & 3) * 32;  // warp N offset (0/32/64/96)

    float acc[4][4][4];
#pragma unroll
    for (int i = 0; i < 4; i++)
#pragma unroll
        for (int j = 0; j < 4; j++)
#pragma unroll
            for (int q = 0; q < 4; q++) acc[i][j][q] = 0.f;

#pragma unroll
    for (int ks = 0; ks < 9; ks++) {
        const int kb = ks * 16;     // k base (bf16 elems)
        uint32_t ah[4][4], al[4][4], bh[4][2], bl[4][2];
#pragma unroll
        for (int i = 0; i < 4; i++) {
            int r = wm + i * 16;
            int o0 = (r + g) * SM_STRIDE + kb + 2 * t;
            int o1 = (r + g + 8) * SM_STRIDE + kb + 2 * t;
            ah[i][0] = *(const uint32_t*)(sAh + o0);
            ah[i][1] = *(const uint32_t*)(sAh + o1);
            ah[i][2] = *(const uint32_t*)(sAh + o0 + 8);
            ah[i][3] = *(const uint32_t*)(sAh + o1 + 8);
            al[i][0] = *(const uint32_t*)(sAl + o0);
            al[i][1] = *(const uint32_t*)(sAl + o1);
            al[i][2] = *(const uint32_t*)(sAl + o0 + 8);
            al[i][3] = *(const uint32_t*)(sAl + o1 + 8);
        }
#pragma unroll
        for (int j = 0; j < 4; j++) {
            int n = wn + j * 8 + g;
            int o = n * SM_STRIDE + kb + 2 * t;
            bh[j][0] = *(const uint32_t*)(sBh + o);
            bh[j][1] = *(const uint32_t*)(sBh + o + 8);
            bl[j][0] = *(const uint32_t*)(sBl + o);
            bl[j][1] = *(const uint32_t*)(sBl + o + 8);
        }
#pragma unroll
        for (int i = 0; i < 4; i++)
#pragma unroll
            for (int j = 0; j < 4; j++) {
                MMA16816(acc[i][j], ah[i], bh[j]);
                MMA16816(acc[i][j], ah[i], bl[j]);
                MMA16816(acc[i][j], al[i], bh[j]);
            }
    }

    // ---- epilogue: bias + relu, direct global stores (float2) ----
#pragma unroll
    for (int j = 0; j < 4; j++) {
        int c = wn + j * 8 + 2 * t;
        float2 bb = *(const float2*)(bias + c);
#pragma unroll
        for (int i = 0; i < 4; i++) {
            int r0 = m0 + wm + i * 16 + g;
            float v0 = acc[i][j][0] + bb.x;
            float v1 = acc[i][j][1] + bb.y;
            float v2 = acc[i][j][2] + bb.x;
            float v3 = acc[i][j][3] + bb.y;
            if (relu) {
                v0 = fmaxf(v0, 0.f); v1 = fmaxf(v1, 0.f);
                v2 = fmaxf(v2, 0.f); v3 = fmaxf(v3, 0.f);
            }
            if (r0 < M)
                *(float2*)(C + (size_t)r0 * 128 + c) = make_float2(v0, v1);
            if (r0 + 8 < M)
                *(float2*)(C + (size_t)(r0 + 8) * 128 + c) = make_float2(v2, v3);
        }
    }
}

// ---------------- launch ----------------
extern "C" void kernel_launch(void* const* d_in, const int* in_sizes, int n_in,
                              void* d_out, int out_size) {
    const float* x  = (const float*)d_in[0];
    const int*   ei = (const int*)d_in[1];
    const float* ea = (const float*)d_in[2];
    const float* W1 = (const float*)d_in[3];
    const float* b1 = (const float*)d_in[4];
    const float* W2 = (const float*)d_in[5];
    const float* b2 = (const float*)d_in[6];
    float* out = (float*)d_out;

    const int AGG_B = (N_NODES * 32 + 255) / 256;   // 6250 (warp per node)
    const int GEMM_B = (N_NODES + 127) / 128;       // 391

    void* p;
    cudaGetSymbolAddress(&p, g_A); float* s_A = (float*)p;
    cudaGetSymbolAddress(&p, g_h); float* s_h = (float*)p;

    cudaFuncSetAttribute(k_gemm_mma, cudaFuncAttributeMaxDynamicSharedMemorySize,
                         GEMM_DYN_SMEM);

    // fused CSR build: detect+zero | hist | scan | scatter (one launch)
    k_csr<<<CSR_BLOCKS, CSR_THREADS>>>(ei);

    // layer 1: aggregate x + edge_attr, then mma GEMM with relu -> g_h
    k_agg<true><<<AGG_B, 256>>>(x, ea);
    k_gemm_mma<<<GEMM_B, 256, GEMM_DYN_SMEM>>>(s_A, W1, b1, s_h, N_NODES, 1);

    // layer 2: aggregate h into cols 0..127 (edge cols 128..143 preserved)
    k_agg<false><<<AGG_B, 256>>>(s_h, nullptr);
    k_gemm_mma<<<GEMM_B, 256, GEMM_DYN_SMEM>>>(s_A, W2, b2, out, N_NODES, 0);
}